// round 2
// baseline (speedup 1.0000x reference)
#include <cuda_runtime.h>
#include <math.h>
#include <stdint.h>

#define BATCH 4
#define T_SAMP 96000
#define NFFT 1024
#define HOP 120
#define NFRAMES 801
#define NBINS 513
#define EPS_F 1.1920928955078125e-07f
#define SLOPE 0.1f
#define PI_D 3.14159265358979323846

// ---- output layout: (flat, fmap0..fmap5) concatenated, float32 ----
#define SZ_FLAT (4*513*101)
#define SZ_F0   (4*32*513*801)
#define SZ_F1   (4*32*513*401)
#define SZ_F2   (4*32*513*201)
#define SZ_F3   (4*32*513*101)
#define SZ_F4   (4*32*513*101)
#define SZ_F5   (4*513*101)
#define OFF_FLAT 0
#define OFF_F0  (OFF_FLAT + SZ_FLAT)
#define OFF_F1  (OFF_F0 + SZ_F0)
#define OFF_F2  (OFF_F1 + SZ_F1)
#define OFF_F3  (OFF_F2 + SZ_F2)
#define OFF_F4  (OFF_F3 + SZ_F3)
#define OFF_F5  (OFF_F4 + SZ_F4)

// ---- device scratch (allocation-free rule: __device__ globals) ----
__device__ float  g_mag[BATCH * NBINS * NFRAMES];   // 6.6 MB
__device__ float2 g_tw[512];
__device__ float  g_win[NFFT];
__device__ float  g_w0[32*7*7];
__device__ float  g_w1[32*32*27];
__device__ float  g_w2[32*32*27];
__device__ float  g_w3[32*32*27];
__device__ float  g_w4[32*32*9];
__device__ float  g_wo[32*9];

// ============================================================
// init: FFT twiddles + Hann window (fp64 trig for accuracy)
// ============================================================
__global__ void init_kernel() {
    int i = threadIdx.x;  // 512 threads
    double ang = -2.0 * PI_D * (double)i / 1024.0;
    g_tw[i] = make_float2((float)cos(ang), (float)sin(ang));
    for (int j = i; j < NFFT; j += 512) {
        float w = 0.0f;
        if (j >= 212 && j < 812) {
            double ph = 2.0 * PI_D * (double)(j - 212) / 600.0;
            w = (float)(0.5 * (1.0 - cos(ph)));
        }
        g_win[j] = w;
    }
}

// ============================================================
// weight norm: w = g * v / ||v||  (per output channel)
// blocks: 0-31 L0, 32-63 L1, 64-95 L2, 96-127 L3, 128-159 L4, 160 Lo
// ============================================================
__global__ void wnorm_kernel(
    const float* __restrict__ v0, const float* __restrict__ gg0,
    const float* __restrict__ v1, const float* __restrict__ gg1,
    const float* __restrict__ v2, const float* __restrict__ gg2,
    const float* __restrict__ v3, const float* __restrict__ gg3,
    const float* __restrict__ v4, const float* __restrict__ gg4,
    const float* __restrict__ vo, const float* __restrict__ ggo)
{
    int bid = blockIdx.x;
    const float* v; const float* g; float* wout; int n; int oc;
    if      (bid < 32)  { v = v0; g = gg0; wout = g_w0; n = 49;  oc = bid; }
    else if (bid < 64)  { v = v1; g = gg1; wout = g_w1; n = 864; oc = bid - 32; }
    else if (bid < 96)  { v = v2; g = gg2; wout = g_w2; n = 864; oc = bid - 64; }
    else if (bid < 128) { v = v3; g = gg3; wout = g_w3; n = 864; oc = bid - 96; }
    else if (bid < 160) { v = v4; g = gg4; wout = g_w4; n = 288; oc = bid - 128; }
    else                { v = vo; g = ggo; wout = g_wo; n = 288; oc = 0; }

    const float* vv = v + (size_t)oc * n;
    float s = 0.0f;
    for (int i = threadIdx.x; i < n; i += 256) { float x = vv[i]; s += x * x; }
    #pragma unroll
    for (int o = 16; o > 0; o >>= 1) s += __shfl_xor_sync(0xffffffffu, s, o);
    __shared__ float red[8];
    if ((threadIdx.x & 31) == 0) red[threadIdx.x >> 5] = s;
    __syncthreads();
    __shared__ float sc_sh;
    if (threadIdx.x == 0) {
        float tot = 0.0f;
        #pragma unroll
        for (int i = 0; i < 8; i++) tot += red[i];
        sc_sh = g[oc] / sqrtf(tot);
    }
    __syncthreads();
    float sc = sc_sh;
    float* wo = wout + (size_t)oc * n;
    for (int i = threadIdx.x; i < n; i += 256) wo[i] = vv[i] * sc;
}

// ============================================================
// STFT: one block per (batch, frame). 512 thr, radix-2 1024-pt FFT in smem.
// Writes mag[b][bin][frame]  (frame contiguous)
// ============================================================
__global__ void stft_kernel(const float* __restrict__ y) {
    __shared__ float2 s[NFFT];
    int b  = blockIdx.x / NFRAMES;
    int fr = blockIdx.x % NFRAMES;
    int tid = threadIdx.x;  // 512

    for (int j = tid; j < NFFT; j += 512) {
        int pos = fr * HOP + j - 512;
        if (pos < 0) pos = -pos;
        else if (pos >= T_SAMP) pos = 2 * T_SAMP - 2 - pos;
        float v = y[b * T_SAMP + pos] * g_win[j];
        int rj = (int)(__brev((unsigned)j) >> 22);  // 10-bit reverse
        s[rj] = make_float2(v, 0.0f);
    }
    __syncthreads();

    #pragma unroll
    for (int st = 1; st <= 10; st++) {
        int half = 1 << (st - 1);
        int j    = tid & (half - 1);
        int blk  = tid >> (st - 1);
        int i0   = (blk << st) + j;
        int i1   = i0 + half;
        float2 tw = g_tw[j << (10 - st)];
        float2 a = s[i0], c = s[i1];
        float tr = tw.x * c.x - tw.y * c.y;
        float ti = tw.x * c.y + tw.y * c.x;
        s[i0] = make_float2(a.x + tr, a.y + ti);
        s[i1] = make_float2(a.x - tr, a.y - ti);
        __syncthreads();
    }

    for (int k = tid; k < NBINS; k += 512) {
        float2 v = s[k];
        float p = fmaxf(v.x * v.x + v.y * v.y, EPS_F);
        g_mag[((size_t)b * NBINS + k) * NFRAMES + fr] = sqrtf(p);
    }
}

// ============================================================
// Harmonic conv + lrelu -> fmap0.
// Shifts >= 513 for kf=0..3 -> those lowered channels are identically zero.
// One block per (b, f). Precombine 3 rows into smem, weights in registers.
// ============================================================
__global__ void hconv_kernel(const float* __restrict__ bias, float* __restrict__ out0) {
    __shared__ float s6[807], s5[807], s4[807];
    int b = blockIdx.x / NBINS;
    int f = blockIdx.x % NBINS;
    int tid = threadIdx.x;  // 256

    double sh4 = 1000.0 * log(7.0 / 5.0);   // 336.472...
    double sh5 = 1000.0 * log(7.0 / 6.0);   // 154.150...
    float fr4 = (float)(sh4 - floor(sh4));
    float fr5 = (float)(sh5 - floor(sh5));

    const float* mb = g_mag + (size_t)b * NBINS * NFRAMES;
    for (int j = tid; j < 807; j += 256) {
        int t = j - 3;
        float x6 = 0.f, x5 = 0.f, x4v = 0.f;
        if (t >= 0 && t < NFRAMES) {
            x6 = mb[f * NFRAMES + t];
            float a = (f >= 154) ? mb[(f - 154) * NFRAMES + t] : 0.f;
            float c = (f >= 155) ? mb[(f - 155) * NFRAMES + t] : 0.f;
            x5 = (1.f - fr5) * a + fr5 * c;
            float d = (f >= 336) ? mb[(f - 336) * NFRAMES + t] : 0.f;
            float e = (f >= 337) ? mb[(f - 337) * NFRAMES + t] : 0.f;
            x4v = (1.f - fr4) * d + fr4 * e;
        }
        s6[j] = x6; s5[j] = x5; s4[j] = x4v;
    }
    __syncthreads();

    for (int co = 0; co < 32; co++) {
        float w4r[7], w5r[7], w6r[7];
        #pragma unroll
        for (int kt = 0; kt < 7; kt++) {
            w4r[kt] = g_w0[(co * 7 + 4) * 7 + kt];
            w5r[kt] = g_w0[(co * 7 + 5) * 7 + kt];
            w6r[kt] = g_w0[(co * 7 + 6) * 7 + kt];
        }
        float bv = bias[co];
        float* o = out0 + ((size_t)(b * 32 + co) * NBINS + f) * NFRAMES;
        for (int t = tid; t < NFRAMES; t += 256) {
            float acc = bv;
            #pragma unroll
            for (int kt = 0; kt < 7; kt++) {
                acc = fmaf(w4r[kt], s4[t + kt], acc);
                acc = fmaf(w5r[kt], s5[t + kt], acc);
                acc = fmaf(w6r[kt], s6[t + kt], acc);
            }
            o[t] = acc > 0.f ? acc : SLOPE * acc;
        }
    }
}

// ============================================================
// 3x9 stride (1,2) pad (1,4) conv + lrelu. 32ci -> 32co, H=513.
// 256 thr: co = tid>>3 (32), tt = tid&7 (8 t-positions). Each thread: 16 f-rows.
// Per-ci smem input tile [18][24] + weight slice [32][27].
// ============================================================
template <int L>
__global__ void __launch_bounds__(256, 4)
conv3x9s2_kernel(const float* __restrict__ in, float* __restrict__ out,
                 const float* __restrict__ bias, int Win, int Wout)
{
    const float* w = (L == 1) ? g_w1 : (L == 2) ? g_w2 : g_w3;
    __shared__ float s_in[18][24];
    __shared__ float s_w[32 * 27];
    int tid = threadIdx.x;
    int tt = tid & 7;
    int co = tid >> 3;
    int t0 = blockIdx.x * 8;
    int f0 = blockIdx.y * 16;
    int b  = blockIdx.z;

    float acc[16];
    float bv = bias[co];
    #pragma unroll
    for (int i = 0; i < 16; i++) acc[i] = bv;

    for (int ci = 0; ci < 32; ci++) {
        __syncthreads();
        const float* ibase = in + (size_t)(b * 32 + ci) * NBINS * Win;
        for (int i = tid; i < 432; i += 256) {
            int r = i / 24, c = i % 24;
            int fi = f0 + r - 1;
            int ti = 2 * t0 + c - 4;
            float v = 0.f;
            if (fi >= 0 && fi < NBINS && ti >= 0 && ti < Win)
                v = ibase[(size_t)fi * Win + ti];
            s_in[r][c] = v;
        }
        for (int i = tid; i < 864; i += 256) {
            int co2 = i / 27, k = i % 27;
            s_w[i] = w[(co2 * 32 + ci) * 27 + k];
        }
        __syncthreads();

        #pragma unroll
        for (int kw = 0; kw < 9; kw++) {
            float col[18];
            #pragma unroll
            for (int r = 0; r < 18; r++) col[r] = s_in[r][2 * tt + kw];
            #pragma unroll
            for (int kh = 0; kh < 3; kh++) {
                float wv = s_w[co * 27 + kh * 9 + kw];
                #pragma unroll
                for (int ff = 0; ff < 16; ff++)
                    acc[ff] = fmaf(wv, col[ff + kh], acc[ff]);
            }
        }
    }

    int t = t0 + tt;
    if (t < Wout) {
        float* obase = out + (size_t)(b * 32 + co) * NBINS * Wout + t;
        #pragma unroll
        for (int ff = 0; ff < 16; ff++) {
            int f = f0 + ff;
            if (f < NBINS) {
                float v = acc[ff];
                v = v > 0.f ? v : SLOPE * v;
                obase[(size_t)f * Wout] = v;
            }
        }
    }
}

// ============================================================
// 3x3 stride 1 pad 1 conv + lrelu, W=101 (layer 4). 16 f-rows per thread.
// ============================================================
__global__ void __launch_bounds__(256, 4)
conv3x3s1_kernel(const float* __restrict__ in, float* __restrict__ out,
                 const float* __restrict__ bias)
{
    const int W = 101;
    __shared__ float s_in[18][12];
    __shared__ float s_w[288];
    int tid = threadIdx.x;
    int tt = tid & 7;
    int co = tid >> 3;
    int t0 = blockIdx.x * 8;
    int f0 = blockIdx.y * 16;
    int b  = blockIdx.z;

    float acc[16];
    float bv = bias[co];
    #pragma unroll
    for (int i = 0; i < 16; i++) acc[i] = bv;

    for (int ci = 0; ci < 32; ci++) {
        __syncthreads();
        const float* ibase = in + (size_t)(b * 32 + ci) * NBINS * W;
        if (tid < 216) {
            int r = tid / 12, c = tid % 12;
            int fi = f0 + r - 1;
            int ti = t0 + c - 1;
            float v = 0.f;
            if (fi >= 0 && fi < NBINS && ti >= 0 && ti < W)
                v = ibase[(size_t)fi * W + ti];
            s_in[r][c] = v;
        }
        for (int i = tid; i < 288; i += 256) {
            int co2 = i / 9, k = i % 9;
            s_w[i] = g_w4[(co2 * 32 + ci) * 9 + k];
        }
        __syncthreads();

        #pragma unroll
        for (int kw = 0; kw < 3; kw++) {
            float col[18];
            #pragma unroll
            for (int r = 0; r < 18; r++) col[r] = s_in[r][tt + kw];
            #pragma unroll
            for (int kh = 0; kh < 3; kh++) {
                float wv = s_w[co * 9 + kh * 3 + kw];
                #pragma unroll
                for (int ff = 0; ff < 16; ff++)
                    acc[ff] = fmaf(wv, col[ff + kh], acc[ff]);
            }
        }
    }

    int t = t0 + tt;
    if (t < W) {
        float* obase = out + (size_t)(b * 32 + co) * NBINS * W + t;
        #pragma unroll
        for (int ff = 0; ff < 16; ff++) {
            int f = f0 + ff;
            if (f < NBINS) {
                float v = acc[ff];
                v = v > 0.f ? v : SLOPE * v;
                obase[(size_t)f * W] = v;
            }
        }
    }
}

// ============================================================
// Output conv (32->1, 3x3, pad 1), no lrelu. Writes fmap5 AND flat.
// ============================================================
__global__ void convo_kernel(const float* __restrict__ in,
                             float* __restrict__ out_f5,
                             float* __restrict__ out_flat,
                             const float* __restrict__ bias)
{
    const int W = 101;
    __shared__ float sw[288];
    int tid = threadIdx.x;
    for (int i = tid; i < 288; i += 256) sw[i] = g_wo[i];
    __syncthreads();

    int idx = blockIdx.x * 256 + tid;
    if (idx >= SZ_F5) return;
    int t = idx % W;
    int f = (idx / W) % NBINS;
    int b = idx / (W * NBINS);
    float acc = bias[0];
    const float* ib = in + (size_t)b * 32 * NBINS * W;
    for (int ci = 0; ci < 32; ci++) {
        #pragma unroll
        for (int kh = 0; kh < 3; kh++) {
            int ff = f + kh - 1;
            if (ff < 0 || ff >= NBINS) continue;
            #pragma unroll
            for (int kw = 0; kw < 3; kw++) {
                int tc = t + kw - 1;
                if (tc < 0 || tc >= W) continue;
                acc = fmaf(sw[ci * 9 + kh * 3 + kw], ib[(ci * NBINS + ff) * W + tc], acc);
            }
        }
    }
    out_f5[idx] = acc;
    out_flat[idx] = acc;
}

// ============================================================
extern "C" void kernel_launch(void* const* d_in, const int* in_sizes, int n_in,
                              void* d_out, int out_size)
{
    const float* y  = (const float*)d_in[0];
    const float* v0 = (const float*)d_in[1];
    const float* g0 = (const float*)d_in[2];
    const float* b0 = (const float*)d_in[3];
    const float* v1 = (const float*)d_in[4];
    const float* g1 = (const float*)d_in[5];
    const float* b1 = (const float*)d_in[6];
    const float* v2 = (const float*)d_in[7];
    const float* g2 = (const float*)d_in[8];
    const float* b2 = (const float*)d_in[9];
    const float* v3 = (const float*)d_in[10];
    const float* g3 = (const float*)d_in[11];
    const float* b3 = (const float*)d_in[12];
    const float* v4 = (const float*)d_in[13];
    const float* g4 = (const float*)d_in[14];
    const float* b4 = (const float*)d_in[15];
    const float* vo = (const float*)d_in[16];
    const float* go = (const float*)d_in[17];
    const float* bo = (const float*)d_in[18];
    float* out = (float*)d_out;

    init_kernel<<<1, 512>>>();
    wnorm_kernel<<<161, 256>>>(v0, g0, v1, g1, v2, g2, v3, g3, v4, g4, vo, go);
    stft_kernel<<<BATCH * NFRAMES, 512>>>(y);
    hconv_kernel<<<BATCH * NBINS, 256>>>(b0, out + OFF_F0);
    conv3x9s2_kernel<1><<<dim3(51, 33, BATCH), 256>>>(out + OFF_F0, out + OFF_F1, b1, 801, 401);
    conv3x9s2_kernel<2><<<dim3(26, 33, BATCH), 256>>>(out + OFF_F1, out + OFF_F2, b2, 401, 201);
    conv3x9s2_kernel<3><<<dim3(13, 33, BATCH), 256>>>(out + OFF_F2, out + OFF_F3, b3, 201, 101);
    conv3x3s1_kernel<<<dim3(13, 33, BATCH), 256>>>(out + OFF_F3, out + OFF_F4, b4);
    convo_kernel<<<(SZ_F5 + 255) / 256, 256>>>(out + OFF_F4, out + OFF_F5, out + OFF_FLAT, bo);
}